// round 6
// baseline (speedup 1.0000x reference)
#include <cuda_runtime.h>

// B-spline layer via per-span cubic collapse:
//   out[b,f] = A0(m,f) + A1 t + A2 t^2 + A3 t^3,  u = 61*x, m = floor(u), t = u-m
// where A_c(m,f) = sum_r basisPoly[m][r][c] * cp[m+r][f]  (bias folded into A0).
// Each block builds the 61x128 float4 coefficient table in smem (125 KB),
// then evaluates with 1 LDS.128 + 3 FMA per element.

#define NF   128
#define NSPAN 61
#define TB   1024
#define RPB  128          // rows per block
#define U    4

#define SMEM_BYTES (NSPAN * NF * 16 + NSPAN * 16 * 4)   // table + basis polys

__device__ __forceinline__ float knotv(float im3) {
    // padded knot value (knot units): clamp(i-3, 0, 61), im3 = i-3 as float
    return fminf(fmaxf(im3, 0.0f), 61.0f);
}

template <bool GUARD>
__global__ void __launch_bounds__(TB, 1)
bspline_kernel(const float* __restrict__ x,
               const float* __restrict__ cp,
               const float* __restrict__ bias,
               float* __restrict__ out,
               int B)
{
    extern __shared__ float smem[];
    float4* __restrict__ table  = (float4*)smem;            // [61*128]
    float*  __restrict__ basisB = smem + NSPAN * NF * 4;    // [61][16] : [m][r*4+c]

    const int tid = threadIdx.x;

    // ---- phase 1: polynomial Cox-de Boor per span (threads 0..60) ----
    if (tid < NSPAN) {
        const float fm = (float)tid;   // span m
        // Bo[j] = poly coeffs (in t) of B_{i}^{k}; fully unrolled so arrays in regs
        float Bo[4][4];
#pragma unroll
        for (int j = 0; j < 4; j++)
#pragma unroll
            for (int c = 0; c < 4; c++) Bo[j][c] = 0.0f;
        Bo[0][0] = 1.0f;               // level 0: B_{m+3}^0 = 1 on the span

#pragma unroll
        for (int k = 1; k <= 3; k++) {
            float Bn[4][4];
#pragma unroll
            for (int j = 0; j < 4; j++)
#pragma unroll
                for (int c = 0; c < 4; c++) Bn[j][c] = 0.0f;
#pragma unroll
            for (int j = 0; j <= k; j++) {
                // i = m + 3 - k + j ; knotv takes (i-3) = m - k + j + const
                const float ti   = knotv(fm + (float)(-k + j));        // t_i
                const float ti1  = knotv(fm + (float)(-k + j + 1));    // t_{i+1}
                const float tik  = knotv(fm + (float)(j));             // t_{i+k}
                const float tik1 = knotv(fm + (float)(j + 1));         // t_{i+k+1}
                if (j >= 1) {      // (u - t_i)/(t_{i+k}-t_i) * Bo[j-1]
                    const float d = tik - ti;
                    if (d != 0.0f) {
                        const float inv = 1.0f / d;
                        const float a0  = (fm - ti) * inv;
#pragma unroll
                        for (int c = 0; c < 4; c++) Bn[j][c] += a0 * Bo[j - 1][c];
#pragma unroll
                        for (int c = 0; c < 3; c++) Bn[j][c + 1] += inv * Bo[j - 1][c];
                    }
                }
                if (j <= k - 1) {  // (t_{i+k+1} - u)/(t_{i+k+1}-t_{i+1}) * Bo[j]
                    const float d = tik1 - ti1;
                    if (d != 0.0f) {
                        const float inv = 1.0f / d;
                        const float b0  = (tik1 - fm) * inv;
#pragma unroll
                        for (int c = 0; c < 4; c++) Bn[j][c] += b0 * Bo[j][c];
#pragma unroll
                        for (int c = 0; c < 3; c++) Bn[j][c + 1] -= inv * Bo[j][c];
                    }
                }
            }
#pragma unroll
            for (int j = 0; j < 4; j++)
#pragma unroll
                for (int c = 0; c < 4; c++) Bo[j][c] = Bn[j][c];
        }
        // Bo[r] = coeffs of basis N_{m+r} restricted to span m
#pragma unroll
        for (int r = 0; r < 4; r++)
#pragma unroll
            for (int c = 0; c < 4; c++)
                basisB[tid * 16 + r * 4 + c] = Bo[r][c];
    }
    __syncthreads();

    // ---- phase 2: fold control points + bias -> float4 table[m][f] ----
    for (int idx = tid; idx < NSPAN * NF; idx += TB) {
        const int m = idx >> 7;
        const int f = idx & (NF - 1);
        const float c0 = cp[(m + 0) * NF + f];
        const float c1 = cp[(m + 1) * NF + f];
        const float c2 = cp[(m + 2) * NF + f];
        const float c3 = cp[(m + 3) * NF + f];
        const float* __restrict__ Bm = &basisB[m * 16];   // broadcast within warp
        float4 A;
        A.x = fmaf(c0, Bm[0], fmaf(c1, Bm[4], fmaf(c2, Bm[8],  fmaf(c3, Bm[12], bias[f]))));
        A.y = fmaf(c0, Bm[1], fmaf(c1, Bm[5], fmaf(c2, Bm[9],  c3 * Bm[13])));
        A.z = fmaf(c0, Bm[2], fmaf(c1, Bm[6], fmaf(c2, Bm[10], c3 * Bm[14])));
        A.w = fmaf(c0, Bm[3], fmaf(c1, Bm[7], fmaf(c2, Bm[11], c3 * Bm[15])));
        table[idx] = A;
    }
    __syncthreads();

    // ---- phase 3: evaluate (1 LDG + 1 LDS.128 + 3 FMA + 1 STG per element) ----
    const int f    = tid & (NF - 1);
    const int lrow = tid >> 7;                       // 0..7
    const int rowBase = blockIdx.x * RPB + lrow;

#pragma unroll
    for (int chunk = 0; chunk < RPB / (8 * U); chunk++) {   // 4 chunks of 4 rows
        const int r0 = rowBase + chunk * (8 * U);

        float xv[U];
#pragma unroll
        for (int j = 0; j < U; j++) {
            const int row = r0 + j * 8;
            if (!GUARD || row < B) xv[j] = x[row * NF + f];
        }

        float t[U];
        float4 A[U];
#pragma unroll
        for (int j = 0; j < U; j++) {
            const float u  = xv[j] * 61.0f;
            const float fm = floorf(u);
            t[j] = u - fm;
            const int m = (int)fm;
            A[j] = table[m * NF + f];                // conflict-free LDS.128
        }

#pragma unroll
        for (int j = 0; j < U; j++) {
            float r = fmaf(A[j].w, t[j], A[j].z);
            r = fmaf(r, t[j], A[j].y);
            r = fmaf(r, t[j], A[j].x);
            const int row = r0 + j * 8;
            if (!GUARD || row < B) out[row * NF + f] = r;
        }
    }
}

extern "C" void kernel_launch(void* const* d_in, const int* in_sizes, int n_in,
                              void* d_out, int out_size)
{
    const float* x    = (const float*)d_in[0];
    const float* cp   = (const float*)d_in[1];
    const float* bias = (const float*)d_in[2];
    float* out = (float*)d_out;

    const int B = in_sizes[0] / NF;   // 16384 rows

    if ((B % RPB) == 0) {
        static int smemSet0 = 0;
        cudaFuncSetAttribute(bspline_kernel<false>,
                             cudaFuncAttributeMaxDynamicSharedMemorySize, SMEM_BYTES);
        (void)smemSet0;
        bspline_kernel<false><<<B / RPB, TB, SMEM_BYTES>>>(x, cp, bias, out, B);
    } else {
        cudaFuncSetAttribute(bspline_kernel<true>,
                             cudaFuncAttributeMaxDynamicSharedMemorySize, SMEM_BYTES);
        bspline_kernel<true><<<(B + RPB - 1) / RPB, TB, SMEM_BYTES>>>(x, cp, bias, out, B);
    }
}

// round 7
// speedup vs baseline: 1.0239x; 1.0239x over previous
#include <cuda_runtime.h>
#include <cstring>

// B-spline layer via per-span cubic collapse:
//   u = 61*x, m = floor(u), t = u-m
//   out[b,f] = A0(m,f) + A1 t + A2 t^2 + A3 t^3
// A_c(m,f) = sum_r basis[m][r][c] * cp[m+r][f], bias folded into A0.
//
// R7: basis polynomials are input-independent -> computed on the HOST (double
// precision Cox-de Boor) and passed as a 3904-byte kernel parameter (constant
// bank, uniform per warp). Device does only: fold cp -> smem table (125 KB),
// then eval with 1 LDS.128 + 3 FMA per element.

#define NF    128
#define NSPAN 61
#define TB    1024
#define RPB   128          // rows per block
#define U     4

#define SMEM_BYTES (NSPAN * NF * 16)

struct BasisTab {
    float4 b[NSPAN * 4];   // [m][r] -> poly coeffs (x,y,z,w) = (c0,c1,c2,c3) in t
};

template <bool GUARD>
__global__ void __launch_bounds__(TB, 1)
bspline_kernel(const BasisTab bt,
               const float* __restrict__ x,
               const float* __restrict__ cp,
               const float* __restrict__ bias,
               float* __restrict__ out,
               int B)
{
    extern __shared__ float4 table[];   // [61*128]
    const int tid = threadIdx.x;

    // ---- fold: cp + bias -> per-span cubic coefficient table ----
    // idx = m*128 + f ; warp-uniform m -> bt loads are LDC broadcasts,
    // cp loads coalesced across f.
#pragma unroll
    for (int it = 0; it < (NSPAN * NF + TB - 1) / TB; it++) {
        const int idx = tid + it * TB;
        if (idx < NSPAN * NF) {
            const int m = idx >> 7;
            const int f = idx & (NF - 1);
            const float c0 = cp[(m + 0) * NF + f];
            const float c1 = cp[(m + 1) * NF + f];
            const float c2 = cp[(m + 2) * NF + f];
            const float c3 = cp[(m + 3) * NF + f];
            const float4 b0 = bt.b[m * 4 + 0];
            const float4 b1 = bt.b[m * 4 + 1];
            const float4 b2 = bt.b[m * 4 + 2];
            const float4 b3 = bt.b[m * 4 + 3];
            float4 A;
            A.x = fmaf(c0, b0.x, fmaf(c1, b1.x, fmaf(c2, b2.x, fmaf(c3, b3.x, bias[f]))));
            A.y = fmaf(c0, b0.y, fmaf(c1, b1.y, fmaf(c2, b2.y, c3 * b3.y)));
            A.z = fmaf(c0, b0.z, fmaf(c1, b1.z, fmaf(c2, b2.z, c3 * b3.z)));
            A.w = fmaf(c0, b0.w, fmaf(c1, b1.w, fmaf(c2, b2.w, c3 * b3.w)));
            table[idx] = A;
        }
    }
    __syncthreads();

    // ---- eval: 1 LDG + 1 LDS.128 + 3 FMA + 1 STG per element ----
    const int f    = tid & (NF - 1);
    const int lrow = tid >> 7;                       // 0..7
    const int rowBase = blockIdx.x * RPB + lrow;

#pragma unroll
    for (int chunk = 0; chunk < RPB / (8 * U); chunk++) {
        const int r0 = rowBase + chunk * (8 * U);

        float xv[U];
#pragma unroll
        for (int j = 0; j < U; j++) {
            const int row = r0 + j * 8;
            if (!GUARD || row < B) xv[j] = x[row * NF + f];
        }

        float t[U];
        float4 A[U];
#pragma unroll
        for (int j = 0; j < U; j++) {
            const float u  = xv[j] * 61.0f;
            const float fm = floorf(u);
            t[j] = u - fm;
            A[j] = table[(int)fm * NF + f];          // conflict-free LDS.128
        }

#pragma unroll
        for (int j = 0; j < U; j++) {
            float r = fmaf(A[j].w, t[j], A[j].z);
            r = fmaf(r, t[j], A[j].y);
            r = fmaf(r, t[j], A[j].x);
            const int row = r0 + j * 8;
            if (!GUARD || row < B) out[row * NF + f] = r;
        }
    }
}

// ---- host-side basis polynomial construction (input-independent) ----
static inline double knotd(int im3) {
    double v = (double)im3;
    if (v < 0.0) v = 0.0;
    if (v > 61.0) v = 61.0;
    return v;
}

static void build_basis(BasisTab* bt)
{
    for (int m = 0; m < NSPAN; m++) {
        // P[j][c]: poly coeffs in t of N_{m+3-k+j}^k on span [m, m+1)
        double P[4][4];
        memset(P, 0, sizeof(P));
        P[0][0] = 1.0;   // k=0: N_{m+3}^0 = 1 on the span

        for (int k = 1; k <= 3; k++) {
            double Q[4][4];
            memset(Q, 0, sizeof(Q));
            for (int j = 0; j <= k; j++) {
                const int i = m + 3 - k + j;
                const double ti   = knotd(i - 3);
                const double ti1  = knotd(i - 2);
                const double tik  = knotd(i - 3 + k);
                const double tik1 = knotd(i - 2 + k);
                if (j >= 1 && tik != ti) {           // (u-t_i)/(t_{i+k}-t_i) * P[j-1]
                    const double inv = 1.0 / (tik - ti);
                    const double a0  = ((double)m - ti) * inv;
                    for (int c = 0; c < 4; c++) Q[j][c]     += a0  * P[j - 1][c];
                    for (int c = 0; c < 3; c++) Q[j][c + 1] += inv * P[j - 1][c];
                }
                if (j <= k - 1 && tik1 != ti1) {     // (t_{i+k+1}-u)/(t_{i+k+1}-t_{i+1}) * P[j]
                    const double inv = 1.0 / (tik1 - ti1);
                    const double b0  = (tik1 - (double)m) * inv;
                    for (int c = 0; c < 4; c++) Q[j][c]     += b0  * P[j][c];
                    for (int c = 0; c < 3; c++) Q[j][c + 1] -= inv * P[j][c];
                }
            }
            memcpy(P, Q, sizeof(P));
        }
        for (int r = 0; r < 4; r++) {
            bt->b[m * 4 + r].x = (float)P[r][0];
            bt->b[m * 4 + r].y = (float)P[r][1];
            bt->b[m * 4 + r].z = (float)P[r][2];
            bt->b[m * 4 + r].w = (float)P[r][3];
        }
    }
}

extern "C" void kernel_launch(void* const* d_in, const int* in_sizes, int n_in,
                              void* d_out, int out_size)
{
    const float* x    = (const float*)d_in[0];
    const float* cp   = (const float*)d_in[1];
    const float* bias = (const float*)d_in[2];
    float* out = (float*)d_out;

    const int B = in_sizes[0] / NF;   // 16384 rows

    static BasisTab bt;
    static bool btInit = false;
    static bool attrSet = false;
    build_basis(&bt);                 // deterministic, recomputed every call
    (void)btInit;

    if (!attrSet) {
        cudaFuncSetAttribute(bspline_kernel<false>,
                             cudaFuncAttributeMaxDynamicSharedMemorySize, SMEM_BYTES);
        cudaFuncSetAttribute(bspline_kernel<true>,
                             cudaFuncAttributeMaxDynamicSharedMemorySize, SMEM_BYTES);
        attrSet = true;
    }

    if ((B % RPB) == 0) {
        bspline_kernel<false><<<B / RPB, TB, SMEM_BYTES>>>(bt, x, cp, bias, out, B);
    } else {
        bspline_kernel<true><<<(B + RPB - 1) / RPB, TB, SMEM_BYTES>>>(bt, x, cp, bias, out, B);
    }
}